// round 7
// baseline (speedup 1.0000x reference)
#include <cuda_runtime.h>
#include <cuda_bf16.h>
#include <cstdint>

// HashGridEncoding R7: spatial bucket sort (32^3) + level-major sorted main.
// Overhead passes minimized: no zero kernel (scan zeroes hist after reading),
// hist 4 pts/thread w/ packed (bucket|rank<<15), scatter 2 pts/thread.

#define NUM_LEVELS 9
#define PMAX 262144
#define NB   32768           // 32^3 buckets

__device__ int    g_hist[NB];     // zeroed by k_scan after use (steady state)
__device__ int    g_off[NB];      // exclusive scan (immutable after k_scan)
__device__ int    g_pk[PMAX];     // bucket | (rank<<15)
__device__ float4 g_xs4[PMAX];    // sorted {x, y, z, bitcast(orig_id)}

__device__ __forceinline__ int bucket_of(float px, float py, float pz)
{
    int cx = min(31, max(0, (int)((px + 1.0f) * 16.0f)));
    int cy = min(31, max(0, (int)((py + 1.0f) * 16.0f)));
    int cz = min(31, max(0, (int)((pz + 1.0f) * 16.0f)));
    return cx + (cy << 5) + (cz << 10);
}

// ---------- pass 1: histogram + rank, 4 points/thread ----------
__global__ void k_hist(const float4* __restrict__ x4, int P)
{
    int t = blockIdx.x * blockDim.x + threadIdx.x;
    int p0 = t * 4;
    if (p0 >= P) return;

    float4 a = x4[t * 3 + 0];
    float4 b = x4[t * 3 + 1];
    float4 c = x4[t * 3 + 2];

    int b0 = bucket_of(a.x, a.y, a.z);
    int b1 = bucket_of(a.w, b.x, b.y);
    int b2 = bucket_of(b.z, b.w, c.x);
    int b3 = bucket_of(c.y, c.z, c.w);

    int4 pk;
    pk.x = b0 | (atomicAdd(&g_hist[b0], 1) << 15);
    pk.y = b1 | (atomicAdd(&g_hist[b1], 1) << 15);
    pk.z = b2 | (atomicAdd(&g_hist[b2], 1) << 15);
    pk.w = b3 | (atomicAdd(&g_hist[b3], 1) << 15);
    ((int4*)g_pk)[t] = pk;
}

// ---------- pass 2: exclusive scan of 32768 counters + zero hist ----------
__global__ void __launch_bounds__(1024) k_scan()
{
    int t = threadIdx.x, lane = t & 31, wid = t >> 5;
    int4* __restrict__ h4 = (int4*)g_hist;
    int4 v[8];
    int base4 = t * 8;
#pragma unroll
    for (int i = 0; i < 8; i++) v[i] = h4[base4 + i];
    int sum = 0;
#pragma unroll
    for (int i = 0; i < 8; i++) sum += v[i].x + v[i].y + v[i].z + v[i].w;

    int inc = sum;
#pragma unroll
    for (int off = 1; off < 32; off <<= 1) {
        int n = __shfl_up_sync(0xFFFFFFFFu, inc, off);
        if (lane >= off) inc += n;
    }
    __shared__ int woff[32];
    if (lane == 31) woff[wid] = inc;
    __syncthreads();
    if (wid == 0) {
        int wv = woff[lane];
        int winc = wv;
#pragma unroll
        for (int off = 1; off < 32; off <<= 1) {
            int n = __shfl_up_sync(0xFFFFFFFFu, winc, off);
            if (lane >= off) winc += n;
        }
        woff[lane] = winc - wv;   // exclusive
    }
    __syncthreads();

    int run = woff[wid] + (inc - sum);
    int4* __restrict__ o4 = (int4*)g_off;
    const int4 z4 = make_int4(0, 0, 0, 0);
#pragma unroll
    for (int i = 0; i < 8; i++) {
        int4 w;
        w.x = run; run += v[i].x;
        w.y = run; run += v[i].y;
        w.z = run; run += v[i].z;
        w.w = run; run += v[i].w;
        o4[base4 + i] = w;
        h4[base4 + i] = z4;       // reset for next replay (no k_zero kernel)
    }
}

// ---------- pass 3: atomic-free scatter, 2 points/thread ----------
__global__ void k_scatter(const float2* __restrict__ x2, int P)
{
    int t = blockIdx.x * blockDim.x + threadIdx.x;
    int p0 = t * 2;
    if (p0 >= P) return;

    int2 pk = ((const int2*)g_pk)[t];
    float2 a = x2[t * 3 + 0];     // (x0, y0)
    float2 b = x2[t * 3 + 1];     // (z0, x1)
    float2 c = x2[t * 3 + 2];     // (y1, z1)

    int b0 = pk.x & 0x7FFF, r0 = pk.x >> 15;
    int b1 = pk.y & 0x7FFF, r1 = pk.y >> 15;
    int pos0 = g_off[b0] + r0;
    int pos1 = g_off[b1] + r1;

    g_xs4[pos0] = make_float4(a.x, a.y, b.x, __int_as_float(p0));
    g_xs4[pos1] = make_float4(b.y, c.x, c.y, __int_as_float(p0 + 1));
}

// ---------- aligned float4 pair load: (q[b], q[b+1]) ----------
__device__ __forceinline__ void load_pair(const float4* __restrict__ t4, int b,
                                          float2& q0, float2& q1)
{
    int a = b >> 1;
    float4 qa = __ldg(t4 + a);
    if (b & 1) {
        float4 qb = __ldg(t4 + a + 1);
        q0 = make_float2(qa.z, qa.w);
        q1 = make_float2(qb.x, qb.y);
    } else {
        q0 = make_float2(qa.x, qa.y);
        q1 = make_float2(qa.z, qa.w);
    }
}

// ---------- pass 4: main, level-major warps over sorted points ----------
__global__ void __launch_bounds__(288) k_main(
    const float* __restrict__ table,
    float* __restrict__ out,
    int P)
{
    __shared__ float  spx[32], spy[32], spz[32];
    __shared__ int    sidx[32];
    __shared__ float2 sres[32][NUM_LEVELS];

    int pbase = blockIdx.x * 32;
    int t = threadIdx.x;

    if (t < 32) {
        int gp = pbase + t;
        float4 f = (gp < P) ? g_xs4[gp] : make_float4(0.f, 0.f, 0.f, 0.f);
        spx[t] = f.x; spy[t] = f.y; spz[t] = f.z;
        sidx[t] = __float_as_int(f.w);
    }
    __syncthreads();

    int w    = t >> 5;          // warp id == level
    int lane = t & 31;          // lane == sorted point within block

    {
        int   vi = 1 << w;
        float vf = (float)vi;

        float gx = (spx[lane] + 1.0f) * 0.5f * vf;
        float gy = (spy[lane] + 1.0f) * 0.5f * vf;
        float gz = (spz[lane] + 1.0f) * 0.5f * vf;

        float bxf = floorf(gx);
        float byf = floorf(gy);
        float bzf = floorf(gz);

        float fx = gx - bxf;
        float fy = gy - byf;
        float fz = gz - bzf;

        int ix = (int)bxf;
        int iy = (int)byf;
        int iz = (int)bzf;

        int flat = ix + iy * vi + iz * vi * vi;
        int dz   = vi * vi;

        const float4* __restrict__ tab4 = (const float4*)table;

        float2 q000, q100, q010, q110, q001, q101, q011, q111;
        load_pair(tab4, flat,           q000, q100);
        load_pair(tab4, flat + vi,      q010, q110);
        load_pair(tab4, flat + dz,      q001, q101);
        load_pair(tab4, flat + dz + vi, q011, q111);

        float wx0 = 1.0f - fx, wx1 = fx;
        float wy0 = 1.0f - fy, wy1 = fy;
        float wz0 = 1.0f - fz, wz1 = fz;

        float a0x = wx0 * q000.x + wx1 * q100.x;
        float a0y = wx0 * q000.y + wx1 * q100.y;
        float a1x = wx0 * q010.x + wx1 * q110.x;
        float a1y = wx0 * q010.y + wx1 * q110.y;
        float a2x = wx0 * q001.x + wx1 * q101.x;
        float a2y = wx0 * q001.y + wx1 * q101.y;
        float a3x = wx0 * q011.x + wx1 * q111.x;
        float a3y = wx0 * q011.y + wx1 * q111.y;

        float b0x = wy0 * a0x + wy1 * a1x;
        float b0y = wy0 * a0y + wy1 * a1y;
        float b1x = wy0 * a2x + wy1 * a3x;
        float b1y = wy0 * a2y + wy1 * a3y;

        sres[lane][w] = make_float2(wz0 * b0x + wz1 * b1x,
                                    wz0 * b0y + wz1 * b1y);
    }
    __syncthreads();

    int pi = t / NUM_LEVELS;
    int li = t - pi * NUM_LEVELS;
    if (pbase + pi < P) {
        float2* __restrict__ o2 = (float2*)out;
        o2[sidx[pi] * NUM_LEVELS + li] = sres[pi][li];
    }
}

extern "C" void kernel_launch(void* const* d_in, const int* in_sizes, int n_in,
                              void* d_out, int out_size)
{
    const float* x     = (const float*)d_in[0];
    const float* table = (const float*)d_in[1];
    float* out         = (float*)d_out;

    int P = in_sizes[0] / 3;
    if (P > PMAX) P = PMAX;

    int histThreads = (P + 3) / 4;
    int scatThreads = (P + 1) / 2;

    k_hist<<<(histThreads + 255) / 256, 256>>>((const float4*)x, P);
    k_scan<<<1, 1024>>>();
    k_scatter<<<(scatThreads + 255) / 256, 256>>>((const float2*)x, P);
    k_main<<<(P + 31) / 32, 288>>>(table, out, P);
}

// round 8
// speedup vs baseline: 1.4697x; 1.4697x over previous
#include <cuda_runtime.h>
#include <cuda_bf16.h>
#include <cstdint>

// HashGridEncoding R8: SINGLE kernel, level-major warps, UNSORTED points.
// R7 evidence: level-major k_main = 28.5us vs point-major 37.3us; hypothesis
// is the warp structure (same-level lanes -> low levels near-broadcast, high
// levels pair-merged LDG.128) drives the gain, not the spatial sort whose
// pipeline overhead (~23us) can never pay for itself.
//
// Block = 288 threads = 9 warps; warp w handles level w for the block's 32
// points. smem-staged x (stride-3, conflict-free) and smem-staged results
// for coalesced 72B/point output.

#define NUM_LEVELS 9

__device__ __forceinline__ void load_pair(const float4* __restrict__ t4, int b,
                                          float2& q0, float2& q1)
{
    int a = b >> 1;
    float4 qa = __ldg(t4 + a);
    if (b & 1) {
        float4 qb = __ldg(t4 + a + 1);       // predicated: odd-b lanes only
        q0 = make_float2(qa.z, qa.w);
        q1 = make_float2(qb.x, qb.y);
    } else {
        q0 = make_float2(qa.x, qa.y);
        q1 = make_float2(qa.z, qa.w);
    }
}

__global__ void __launch_bounds__(288) hashgrid_kernel(
    const float* __restrict__ x,
    const float* __restrict__ table,
    float* __restrict__ out,
    int P)
{
    __shared__ float  sx[96];                  // 32 points x 3 coords
    __shared__ float2 sres[32][NUM_LEVELS];

    int pbase = blockIdx.x * 32;
    int t = threadIdx.x;

    if (t < 96) {
        int g = pbase * 3 + t;
        sx[t] = (g < P * 3) ? x[g] : 0.0f;
    }
    __syncthreads();

    int w    = t >> 5;          // warp id == level (0..8)
    int lane = t & 31;          // lane == point within block

    {
        int   vi = 1 << w;
        float vf = (float)vi;

        float gx = (sx[lane * 3 + 0] + 1.0f) * 0.5f * vf;
        float gy = (sx[lane * 3 + 1] + 1.0f) * 0.5f * vf;
        float gz = (sx[lane * 3 + 2] + 1.0f) * 0.5f * vf;

        float bxf = floorf(gx);
        float byf = floorf(gy);
        float bzf = floorf(gz);

        float fx = gx - bxf;
        float fy = gy - byf;
        float fz = gz - bzf;

        int ix = (int)bxf;
        int iy = (int)byf;
        int iz = (int)bzf;

        int flat = ix + iy * vi + iz * vi * vi;
        int dz   = vi * vi;

        const float4* __restrict__ tab4 = (const float4*)table;

        float2 q000, q100, q010, q110, q001, q101, q011, q111;
        load_pair(tab4, flat,           q000, q100);
        load_pair(tab4, flat + vi,      q010, q110);
        load_pair(tab4, flat + dz,      q001, q101);
        load_pair(tab4, flat + dz + vi, q011, q111);

        float wx0 = 1.0f - fx, wx1 = fx;
        float wy0 = 1.0f - fy, wy1 = fy;
        float wz0 = 1.0f - fz, wz1 = fz;

        float a0x = wx0 * q000.x + wx1 * q100.x;
        float a0y = wx0 * q000.y + wx1 * q100.y;
        float a1x = wx0 * q010.x + wx1 * q110.x;
        float a1y = wx0 * q010.y + wx1 * q110.y;
        float a2x = wx0 * q001.x + wx1 * q101.x;
        float a2y = wx0 * q001.y + wx1 * q101.y;
        float a3x = wx0 * q011.x + wx1 * q111.x;
        float a3y = wx0 * q011.y + wx1 * q111.y;

        float b0x = wy0 * a0x + wy1 * a1x;
        float b0y = wy0 * a0y + wy1 * a1y;
        float b1x = wy0 * a2x + wy1 * a3x;
        float b1y = wy0 * a2y + wy1 * a3y;

        sres[lane][w] = make_float2(wz0 * b0x + wz1 * b1x,
                                    wz0 * b0y + wz1 * b1y);
    }
    __syncthreads();

    // write-out: thread t -> point t/9, level t%9 (9 threads = 72B contiguous,
    // block writes 2304B coalesced to out[pbase..pbase+32))
    int pi = t / NUM_LEVELS;
    int li = t - pi * NUM_LEVELS;
    int p  = pbase + pi;
    if (p < P) {
        float2* __restrict__ o2 = (float2*)out;
        o2[p * NUM_LEVELS + li] = sres[pi][li];
    }
}

extern "C" void kernel_launch(void* const* d_in, const int* in_sizes, int n_in,
                              void* d_out, int out_size)
{
    const float* x     = (const float*)d_in[0];
    const float* table = (const float*)d_in[1];
    float* out         = (float*)d_out;

    int P = in_sizes[0] / 3;
    int blocks = (P + 31) / 32;        // 32 points per block, 9 warps
    hashgrid_kernel<<<blocks, 288>>>(x, table, out, P);
}